// round 12
// baseline (speedup 1.0000x reference)
#include <cuda_runtime.h>
#include <cuda_bf16.h>
#include <cstdint>

#define TT   512
#define BB   128
#define DIN  64
#define NN   512
#define DOUT 2
#define GRID 48
#define NTHR 256

typedef __nv_bfloat16 bf16;

// ---------------- persistent device scratch ----------------
__device__ bf16   g_r_hi[3][3 * BB * NN];     // rates, TRIPLE buffered (slot = t % 3)
__device__ bf16   g_r_lo[3][3 * BB * NN];
__device__ bf16   g_Wrec_hi[3][NN * NN];
__device__ bf16   g_Wrec_lo[3][NN * NN];
__device__ bf16   g_Wcross_hi[3][NN * NN];   // [0]=W_CA, [1]=W_AB, [2]=W_BC
__device__ bf16   g_Wcross_lo[3][NN * NN];
__device__ float  g_Xin[(size_t)TT * BB * NN];
__device__ float  g_hist[(size_t)(TT - 1) * BB * NN];
__device__ unsigned g_flag[3];                // per-region monotonic arrival counters

// ---------------- small asm helpers ----------------
__device__ __forceinline__ uint32_t smaddr(const void* p) {
    return (uint32_t)__cvta_generic_to_shared(p);
}
__device__ __forceinline__ void cp_async16(void* s, const void* g) {
    asm volatile("cp.async.cg.shared.global [%0], [%1], 16;\n" :: "r"(smaddr(s)), "l"(g));
}
__device__ __forceinline__ void cp_commit() { asm volatile("cp.async.commit_group;\n"); }
template<int N>
__device__ __forceinline__ void cp_wait() { asm volatile("cp.async.wait_group %0;\n" :: "n"(N)); }
__device__ __forceinline__ void ldsm_x4(uint32_t* r, uint32_t addr) {
    asm volatile("ldmatrix.sync.aligned.m8n8.x4.shared.b16 {%0,%1,%2,%3}, [%4];\n"
                 : "=r"(r[0]), "=r"(r[1]), "=r"(r[2]), "=r"(r[3]) : "r"(addr));
}
__device__ __forceinline__ void mma_bf16(float c[4], const uint32_t a[4], const uint32_t b[2]) {
    asm volatile(
        "mma.sync.aligned.m16n8k16.row.col.f32.bf16.bf16.f32 "
        "{%0,%1,%2,%3}, {%4,%5,%6,%7}, {%8,%9}, {%0,%1,%2,%3};\n"
        : "+f"(c[0]), "+f"(c[1]), "+f"(c[2]), "+f"(c[3])
        : "r"(a[0]), "r"(a[1]), "r"(a[2]), "r"(a[3]), "r"(b[0]), "r"(b[1]));
}

// fast tanh: 1 - 2/(e^{2x}+1). __expf saturates cleanly at +-inf.
__device__ __forceinline__ float ftanh(float x) {
    float e = __expf(2.f * x);
    return 1.f - __fdividef(2.f, e + 1.f);
}

__device__ __forceinline__ unsigned ld_acq(unsigned* p) {
    unsigned v;
    asm volatile("ld.acquire.gpu.global.u32 %0, [%1];\n" : "=r"(v) : "l"(p) : "memory");
    return v;
}
__device__ __forceinline__ void red_rel_add(unsigned* p) {
    asm volatile("red.release.gpu.global.add.u32 [%0], 1;\n" :: "l"(p) : "memory");
}

// swizzled smem offset (elements). tile row stride = 64 bf16 = 8 x 16B units.
__device__ __forceinline__ int swz(int row, int k) {
    return row * 64 + (((k >> 3) ^ (row & 7)) << 3) + (k & 7);
}

// ---------------- init ----------------
__global__ void init_zero() {
    int i = blockIdx.x * blockDim.x + threadIdx.x;
    if (i < 3 * BB * NN) {
        g_r_hi[0][i] = __float2bfloat16(0.f);
        g_r_lo[0][i] = __float2bfloat16(0.f);
    }
    if (i < 3) g_flag[i] = 0;
}

// ---------------- weight split fp32 -> bf16 hi/lo ----------------
__global__ void split_w(const float* a, const float* b, const float* c,
                        const float* ca, const float* ab, const float* bc) {
    int i = blockIdx.x * blockDim.x + threadIdx.x; // 6 * 262144
    int m = i >> 18;
    int j = i & 262143;
    const float* srcs[6] = {a, b, c, ca, ab, bc};
    float w = srcs[m][j];
    bf16 hi = __float2bfloat16(w);
    bf16 lo = __float2bfloat16(w - __bfloat162float(hi));
    if (m < 3) { g_Wrec_hi[m][j] = hi; g_Wrec_lo[m][j] = lo; }
    else       { g_Wcross_hi[m - 3][j] = hi; g_Wcross_lo[m - 3][j] = lo; }
}

// ---------------- precompute Xin = X @ W_in_A.T (fp32) ----------------
__global__ __launch_bounds__(256) void precompute_in(const float* X, const float* Win) {
    __shared__ float sX[64][68];
    __shared__ float sWt[64][72]; // transposed: [d][n]
    int rb = blockIdx.x * 64;
    int cb = blockIdx.y * 64;
    int tid = threadIdx.x;

    for (int v = tid; v < 1024; v += 256) {
        int row = v >> 4, d4 = (v & 15) * 4;
        float4 tx = *(const float4*)(X + (size_t)(rb + row) * DIN + d4);
        sX[row][d4 + 0] = tx.x; sX[row][d4 + 1] = tx.y;
        sX[row][d4 + 2] = tx.z; sX[row][d4 + 3] = tx.w;
    }
    for (int v = tid; v < 1024; v += 256) {
        int n = v >> 4, d4 = (v & 15) * 4;
        float4 tw = *(const float4*)(Win + (size_t)(cb + n) * DIN + d4);
        sWt[d4 + 0][n] = tw.x; sWt[d4 + 1][n] = tw.y;
        sWt[d4 + 2][n] = tw.z; sWt[d4 + 3][n] = tw.w;
    }
    __syncthreads();

    int ty = tid >> 4, tx = tid & 15;
    float acc[4][4];
#pragma unroll
    for (int i = 0; i < 4; i++)
#pragma unroll
        for (int j = 0; j < 4; j++) acc[i][j] = 0.f;

    for (int k = 0; k < 64; k++) {
        float a0 = sX[ty * 4 + 0][k], a1 = sX[ty * 4 + 1][k];
        float a2 = sX[ty * 4 + 2][k], a3 = sX[ty * 4 + 3][k];
        float4 bq = *(const float4*)&sWt[k][tx * 4];
        acc[0][0] += a0 * bq.x; acc[0][1] += a0 * bq.y; acc[0][2] += a0 * bq.z; acc[0][3] += a0 * bq.w;
        acc[1][0] += a1 * bq.x; acc[1][1] += a1 * bq.y; acc[1][2] += a1 * bq.z; acc[1][3] += a1 * bq.w;
        acc[2][0] += a2 * bq.x; acc[2][1] += a2 * bq.y; acc[2][2] += a2 * bq.z; acc[2][3] += a2 * bq.w;
        acc[3][0] += a3 * bq.x; acc[3][1] += a3 * bq.y; acc[3][2] += a3 * bq.z; acc[3][3] += a3 * bq.w;
    }
#pragma unroll
    for (int i = 0; i < 4; i++)
#pragma unroll
        for (int j = 0; j < 4; j++)
            g_Xin[(size_t)(rb + ty * 4 + i) * NN + cb + tx * 4 + j] = acc[i][j];
}

// ---------------- persistent fused RNN kernel ----------------
// grid = 48: region (3) x coltile (16). CTA tile = [128 rows x 32 cols].
// 256 threads = 8 warps; warp owns rows wr*16..+16, all 32 cols (R6 per-warp
// shape — 2 warps/SMSP for stall covering at CONSTANT per-warp work).
// Warp-autonomous; 3-deep 64-K-chunk cp.async ring; prefetch c+3 AFTER chunk
// c's mma (ordering load-bearing). Step sync: per-region flags (16 arrivals).
// smem (bf16 elems):
//   W slots: 32 x 2048 at 0        (slot = (mat*8+kc64)*2+part), 32 rows x 64 K
//   A bufs : 3 x 2 x 8192 at 65536 (buf, part), 128 rows x 64 K
#define W_SLOT(mat, kc, part) ((((mat) * 8 + (kc)) * 2 + (part)) * 2048)
#define A_OFF 65536
#define A_SLOT(buf, part) (A_OFF + ((buf) * 2 + (part)) * 8192)
#define SMEM_TOTAL ((A_OFF + 6 * 8192) * 2)   // bytes = 229376

// warp loads its own 16 rows of one 64-K chunk (hi+lo): 256 16B units / 32 lanes
__device__ __forceinline__ void load_A_warp(const bf16* hi, const bf16* lo,
                                            int wr, int kb, bf16* sm,
                                            int buf, int lane) {
#pragma unroll
    for (int u = lane; u < 256; u += 32) {
        int part = u >> 7;                  // 0:hi 1:lo
        int w    = u & 127;
        int row  = w >> 3, kk = (w & 7) << 3;
        const bf16* src = (part ? lo : hi) +
            (size_t)(wr * 16 + row) * NN + kb + kk;
        cp_async16(sm + A_SLOT(buf, part) + swz(wr * 16 + row, kk), src);
    }
}

// load all 6 fragments (24 regs) for k16 index kk (0..3) of chunk c in buffer buf
__device__ __forceinline__ void ld6(uint32_t* F, const bf16* sm, int buf, int c, int kk,
                                    int ar, int ak_off, int brow0, int bk_off) {
    int ko  = kk << 4;
    int mat = c >> 3;
    int kc  = c & 7;
    const bf16* Ah = sm + A_SLOT(buf, 0);
    const bf16* Al = sm + A_SLOT(buf, 1);
    const bf16* wh = sm + W_SLOT(mat, kc, 0);
    const bf16* wl = sm + W_SLOT(mat, kc, 1);
    ldsm_x4(F + 0,  smaddr(Ah + swz(ar, ko + ak_off)));
    ldsm_x4(F + 4,  smaddr(Al + swz(ar, ko + ak_off)));
    ldsm_x4(F + 8,  smaddr(wh + swz(brow0,      ko + bk_off)));
    ldsm_x4(F + 12, smaddr(wh + swz(brow0 + 16, ko + bk_off)));
    ldsm_x4(F + 16, smaddr(wl + swz(brow0,      ko + bk_off)));
    ldsm_x4(F + 20, smaddr(wl + swz(brow0 + 16, ko + bk_off)));
}

// the 12 mma for one k16 (3-term split: hh, hl, lh)
__device__ __forceinline__ void mma12(float acc[4][4], const uint32_t* F) {
    mma_bf16(acc[0], F + 0, F + 8);
    mma_bf16(acc[1], F + 0, F + 10);
    mma_bf16(acc[2], F + 0, F + 12);
    mma_bf16(acc[3], F + 0, F + 14);
    mma_bf16(acc[0], F + 0, F + 16);
    mma_bf16(acc[1], F + 0, F + 18);
    mma_bf16(acc[2], F + 0, F + 20);
    mma_bf16(acc[3], F + 0, F + 22);
    mma_bf16(acc[0], F + 4, F + 8);
    mma_bf16(acc[1], F + 4, F + 10);
    mma_bf16(acc[2], F + 4, F + 12);
    mma_bf16(acc[3], F + 4, F + 14);
}

__global__ __launch_bounds__(NTHR, 1) void persist_kernel() {
    extern __shared__ bf16 sm[];
    int tid  = threadIdx.x;
    int lane = tid & 31, warp = tid >> 5;   // 8 warps
    int region = blockIdx.x >> 4;
    int ct     = blockIdx.x & 15;
    int cb = ct * 32;
    int cross = (region + 2) % 3;          // A<-C, B<-A, C<-B
    int nxt   = (region + 1) % 3;          // region that READS our rates
    int wr = warp;                          // warp owns rows wr*16..+16, all 32 cols

    // ---- load resident weights into smem (once) ----
    for (int l = tid; l < 8192; l += NTHR) {
        int slot   = l >> 8;               // 0..31
        int within = l & 255;
        int row = within >> 3, kk = (within & 7) << 3;
        int part   = slot & 1;
        int kc     = (slot >> 1) & 7;
        int mat    = slot >> 4;
        const bf16* src =
            (mat == 0) ? (part ? g_Wrec_lo[region]   : g_Wrec_hi[region])
                       : (part ? g_Wcross_lo[region] : g_Wcross_hi[region]);
        cp_async16(sm + W_SLOT(mat, kc, part) + swz(row, kk),
                   src + (size_t)(cb + row) * NN + kc * 64 + kk);
    }
    cp_commit();
    cp_wait<0>();
    __syncthreads();

    // ---- persistent leaky state in registers (16 outputs per thread) ----
    float xreg[16];
#pragma unroll
    for (int i = 0; i < 16; i++) xreg[i] = 0.f;

    // fragment addressing (constant across steps)
    int ar = wr * 16 + (lane & 15);
    int ak_off = (lane >> 4) << 3;
    int brow0 = ((lane >> 4) << 3) + (lane & 7);   // n 0-15 block
    int bk_off = ((lane >> 3) & 1) << 3;

    int g = lane >> 2, q = lane & 3;
    int row0 = wr * 16 + g;                        // batch row (and +8)

    for (int t = 1; t < TT; t++) {
        // ---- decentralized step gate: producers at t-1, WAR reader at t-2 ----
        if (tid == 0) {
            unsigned tgt1 = 16u * (unsigned)(t - 1);
            while (ld_acq(&g_flag[region]) < tgt1) {}
            while (ld_acq(&g_flag[cross])  < tgt1) {}
            if (t >= 2) {
                unsigned tgt2 = 16u * (unsigned)(t - 2);
                while (ld_acq(&g_flag[nxt]) < tgt2) {}
            }
        }
        __syncthreads();

        int p_in = (t - 1) % 3, p_out = t % 3;
        const bf16* rhi[2] = { &g_r_hi[p_in][region * BB * NN], &g_r_hi[p_in][cross * BB * NN] };
        const bf16* rlo[2] = { &g_r_lo[p_in][region * BB * NN], &g_r_lo[p_in][cross * BB * NN] };

        // prefetch Xin for this step (region 0) — overlaps with mma loop
        float xin[16];
        if (region == 0) {
            const float* xp = g_Xin + (size_t)t * BB * NN;
#pragma unroll
            for (int nh = 0; nh < 4; nh++)
#pragma unroll
                for (int i2 = 0; i2 < 2; i2++) {
                    float2 v = *(const float2*)(xp + (size_t)(row0 + i2 * 8) * NN
                                                + cb + nh * 8 + q * 2);
                    xin[nh * 4 + i2 * 2 + 0] = v.x;
                    xin[nh * 4 + i2 * 2 + 1] = v.y;
                }
        }

        float acc[4][4];
#pragma unroll
        for (int nh = 0; nh < 4; nh++)
#pragma unroll
            for (int i = 0; i < 4; i++) acc[nh][i] = 0.f;

        // prologue: 3-deep per-warp pipeline (chunks 0,1,2)
        load_A_warp(rhi[0], rlo[0], wr, 0,   sm, 0, lane); cp_commit();
        load_A_warp(rhi[0], rlo[0], wr, 64,  sm, 1, lane); cp_commit();
        load_A_warp(rhi[0], rlo[0], wr, 128, sm, 2, lane); cp_commit();

        uint32_t F0[24], F1[24];
        int buf = 0;
#pragma unroll 1
        for (int c = 0; c < 16; c++) {          // 16 chunks x 64 K
            cp_wait<2>();                        // chunk c landed (own warp's groups)
            __syncwarp();

            // software-pipelined 4 x k16: ldsm(kk+1) issued before mma(kk)
            ld6(F0, sm, buf, c, 0, ar, ak_off, brow0, bk_off);
#pragma unroll
            for (int kk = 0; kk < 4; kk++) {
                uint32_t* cur = (kk & 1) ? F1 : F0;
                uint32_t* nxtF = (kk & 1) ? F0 : F1;
                if (kk < 3)
                    ld6(nxtF, sm, buf, c, kk + 1, ar, ak_off, brow0, bk_off);
                mma12(acc, cur);
            }

            // prefetch into the just-freed buffer (AFTER the reads — ordering
            // is load-bearing; issuing before the mma loop is a race)
            if (c < 13) {
                int c3 = c + 3;
                int m2 = c3 >> 3;
                int kb = (c3 & 7) * 64;
                load_A_warp(rhi[m2], rlo[m2], wr, kb, sm, buf, lane);
                cp_commit();
            }
            if (++buf == 3) buf = 0;
        }

        // ---- epilogue: leaky update + fast tanh + split-store rates ----
#pragma unroll
        for (int nh = 0; nh < 4; nh++) {
#pragma unroll
            for (int i2 = 0; i2 < 2; i2++) {
                int row = row0 + i2 * 8;
                int col = cb + nh * 8 + q * 2;
                float s0 = acc[nh][i2 * 2 + 0];
                float s1 = acc[nh][i2 * 2 + 1];
                if (region == 0) {
                    s0 += xin[nh * 4 + i2 * 2 + 0];
                    s1 += xin[nh * 4 + i2 * 2 + 1];
                }
                int xi = nh * 4 + i2 * 2;
                float x0 = 0.9f * xreg[xi + 0] + 0.1f * s0;
                float x1 = 0.9f * xreg[xi + 1] + 0.1f * s1;
                xreg[xi + 0] = x0;
                xreg[xi + 1] = x1;
                float r0 = ftanh(x0), r1 = ftanh(x1);
                bf16 h0 = __float2bfloat16(r0);
                bf16 h1 = __float2bfloat16(r1);
                bf16 l0 = __float2bfloat16(r0 - __bfloat162float(h0));
                bf16 l1 = __float2bfloat16(r1 - __bfloat162float(h1));
                int idx = region * BB * NN + row * NN + col;
                *(__nv_bfloat162*)&g_r_hi[p_out][idx] = __nv_bfloat162(h0, h1);
                *(__nv_bfloat162*)&g_r_lo[p_out][idx] = __nv_bfloat162(l0, l1);
                if (region == 2)
                    *(float2*)&g_hist[(size_t)(t - 1) * BB * NN + (size_t)row * NN + col] =
                        make_float2(r0, r1);
            }
        }

        // publish: all stores visible GPU-wide, then bump region flag
        __threadfence();
        __syncthreads();
        if (tid == 0) red_rel_add(&g_flag[region]);
    }
}

// ---------------- final readout: out = rC_hist @ W_out.T ----------------
__global__ void out_kernel(const float* Wout, float* out) {
    __shared__ float sw0[512], sw1[512];
    int bt = blockIdx.x;
    int tid = threadIdx.x; // 128 threads, one batch row each
    for (int j = tid; j < 512; j += 128) { sw0[j] = Wout[j]; sw1[j] = Wout[512 + j]; }
    __syncthreads();
    const float* row = g_hist + (size_t)bt * BB * NN + (size_t)tid * NN;
    float s0 = 0.f, s1 = 0.f;
    for (int j = 0; j < 512; j += 4) {
        float4 v = *(const float4*)(row + j);
        s0 += v.x * sw0[j] + v.y * sw0[j + 1] + v.z * sw0[j + 2] + v.w * sw0[j + 3];
        s1 += v.x * sw1[j] + v.y * sw1[j + 1] + v.z * sw1[j + 2] + v.w * sw1[j + 3];
    }
    out[((size_t)bt * BB + tid) * 2 + 0] = s0;
    out[((size_t)bt * BB + tid) * 2 + 1] = s1;
}

// ---------------- launch ----------------
extern "C" void kernel_launch(void* const* d_in, const int* in_sizes, int n_in,
                              void* d_out, int out_size) {
    const float* X     = (const float*)d_in[0];
    const float* WrecA = (const float*)d_in[1];
    const float* WrecB = (const float*)d_in[2];
    const float* WrecC = (const float*)d_in[3];
    const float* W_AB  = (const float*)d_in[4];
    const float* W_BC  = (const float*)d_in[5];
    const float* W_CA  = (const float*)d_in[6];
    const float* W_in  = (const float*)d_in[7];
    const float* W_out = (const float*)d_in[8];

    cudaFuncSetAttribute(persist_kernel, cudaFuncAttributeMaxDynamicSharedMemorySize, SMEM_TOTAL);

    init_zero<<<768, 256>>>();
    split_w<<<6144, 256>>>(WrecA, WrecB, WrecC, W_CA, W_AB, W_BC);
    dim3 pg(TT * BB / 64, NN / 64);
    precompute_in<<<pg, 256>>>(X, W_in);
    persist_kernel<<<GRID, NTHR, SMEM_TOTAL>>>();
    out_kernel<<<TT - 1, 128>>>(W_out, (float*)d_out);
}

// round 13
// speedup vs baseline: 1.6940x; 1.6940x over previous
#include <cuda_runtime.h>
#include <cuda_bf16.h>
#include <cstdint>

#define TT   512
#define BB   128
#define DIN  64
#define NN   512
#define DOUT 2
#define GRID 96
#define NTHR 128
#define ARRV 128   // warp arrivals per region per step: 32 CTAs x 4 warps

typedef __nv_bfloat16 bf16;

// ---------------- persistent device scratch ----------------
__device__ bf16   g_r_hi[3][3 * BB * NN];     // rates, TRIPLE buffered (slot = t % 3)
__device__ bf16   g_r_lo[3][3 * BB * NN];
__device__ bf16   g_Wrec_hi[3][NN * NN];
__device__ bf16   g_Wrec_lo[3][NN * NN];
__device__ bf16   g_Wcross_hi[3][NN * NN];   // [0]=W_CA, [1]=W_AB, [2]=W_BC
__device__ bf16   g_Wcross_lo[3][NN * NN];
__device__ float  g_Xin[(size_t)TT * BB * NN];
__device__ float  g_hist[(size_t)(TT - 1) * BB * NN];
__device__ unsigned g_flag[3];                // per-region monotonic WARP arrival counters

// ---------------- small asm helpers ----------------
__device__ __forceinline__ uint32_t smaddr(const void* p) {
    return (uint32_t)__cvta_generic_to_shared(p);
}
__device__ __forceinline__ void cp_async16(void* s, const void* g) {
    asm volatile("cp.async.cg.shared.global [%0], [%1], 16;\n" :: "r"(smaddr(s)), "l"(g));
}
__device__ __forceinline__ void cp_commit() { asm volatile("cp.async.commit_group;\n"); }
template<int N>
__device__ __forceinline__ void cp_wait() { asm volatile("cp.async.wait_group %0;\n" :: "n"(N)); }
__device__ __forceinline__ void ldsm_x4(uint32_t* r, uint32_t addr) {
    asm volatile("ldmatrix.sync.aligned.m8n8.x4.shared.b16 {%0,%1,%2,%3}, [%4];\n"
                 : "=r"(r[0]), "=r"(r[1]), "=r"(r[2]), "=r"(r[3]) : "r"(addr));
}
__device__ __forceinline__ void mma_bf16(float c[4], const uint32_t a[4], const uint32_t b[2]) {
    asm volatile(
        "mma.sync.aligned.m16n8k16.row.col.f32.bf16.bf16.f32 "
        "{%0,%1,%2,%3}, {%4,%5,%6,%7}, {%8,%9}, {%0,%1,%2,%3};\n"
        : "+f"(c[0]), "+f"(c[1]), "+f"(c[2]), "+f"(c[3])
        : "r"(a[0]), "r"(a[1]), "r"(a[2]), "r"(a[3]), "r"(b[0]), "r"(b[1]));
}

// fast tanh: 1 - 2/(e^{2x}+1). __expf saturates cleanly at +-inf.
__device__ __forceinline__ float ftanh(float x) {
    float e = __expf(2.f * x);
    return 1.f - __fdividef(2.f, e + 1.f);
}

__device__ __forceinline__ unsigned ld_acq(unsigned* p) {
    unsigned v;
    asm volatile("ld.acquire.gpu.global.u32 %0, [%1];\n" : "=r"(v) : "l"(p) : "memory");
    return v;
}
__device__ __forceinline__ void red_rel_add(unsigned* p) {
    asm volatile("red.release.gpu.global.add.u32 [%0], 1;\n" :: "l"(p) : "memory");
}
// warp-converged acquire poll until *p >= tgt
__device__ __forceinline__ void wait_flag(unsigned* p, unsigned tgt) {
    while (ld_acq(p) < tgt) {}
    __syncwarp();
}

// swizzled smem offset (elements). tile row stride = 64 bf16 = 8 x 16B units.
__device__ __forceinline__ int swz(int row, int k) {
    return row * 64 + (((k >> 3) ^ (row & 7)) << 3) + (k & 7);
}

// ---------------- init ----------------
__global__ void init_zero() {
    int i = blockIdx.x * blockDim.x + threadIdx.x;
    if (i < 3 * BB * NN) {
        g_r_hi[0][i] = __float2bfloat16(0.f);
        g_r_lo[0][i] = __float2bfloat16(0.f);
    }
    if (i < 3) g_flag[i] = 0;
}

// ---------------- weight split fp32 -> bf16 hi/lo ----------------
__global__ void split_w(const float* a, const float* b, const float* c,
                        const float* ca, const float* ab, const float* bc) {
    int i = blockIdx.x * blockDim.x + threadIdx.x; // 6 * 262144
    int m = i >> 18;
    int j = i & 262143;
    const float* srcs[6] = {a, b, c, ca, ab, bc};
    float w = srcs[m][j];
    bf16 hi = __float2bfloat16(w);
    bf16 lo = __float2bfloat16(w - __bfloat162float(hi));
    if (m < 3) { g_Wrec_hi[m][j] = hi; g_Wrec_lo[m][j] = lo; }
    else       { g_Wcross_hi[m - 3][j] = hi; g_Wcross_lo[m - 3][j] = lo; }
}

// ---------------- precompute Xin = X @ W_in_A.T (fp32) ----------------
__global__ __launch_bounds__(256) void precompute_in(const float* X, const float* Win) {
    __shared__ float sX[64][68];
    __shared__ float sWt[64][72]; // transposed: [d][n]
    int rb = blockIdx.x * 64;
    int cb = blockIdx.y * 64;
    int tid = threadIdx.x;

    for (int v = tid; v < 1024; v += 256) {
        int row = v >> 4, d4 = (v & 15) * 4;
        float4 tx = *(const float4*)(X + (size_t)(rb + row) * DIN + d4);
        sX[row][d4 + 0] = tx.x; sX[row][d4 + 1] = tx.y;
        sX[row][d4 + 2] = tx.z; sX[row][d4 + 3] = tx.w;
    }
    for (int v = tid; v < 1024; v += 256) {
        int n = v >> 4, d4 = (v & 15) * 4;
        float4 tw = *(const float4*)(Win + (size_t)(cb + n) * DIN + d4);
        sWt[d4 + 0][n] = tw.x; sWt[d4 + 1][n] = tw.y;
        sWt[d4 + 2][n] = tw.z; sWt[d4 + 3][n] = tw.w;
    }
    __syncthreads();

    int ty = tid >> 4, tx = tid & 15;
    float acc[4][4];
#pragma unroll
    for (int i = 0; i < 4; i++)
#pragma unroll
        for (int j = 0; j < 4; j++) acc[i][j] = 0.f;

    for (int k = 0; k < 64; k++) {
        float a0 = sX[ty * 4 + 0][k], a1 = sX[ty * 4 + 1][k];
        float a2 = sX[ty * 4 + 2][k], a3 = sX[ty * 4 + 3][k];
        float4 bq = *(const float4*)&sWt[k][tx * 4];
        acc[0][0] += a0 * bq.x; acc[0][1] += a0 * bq.y; acc[0][2] += a0 * bq.z; acc[0][3] += a0 * bq.w;
        acc[1][0] += a1 * bq.x; acc[1][1] += a1 * bq.y; acc[1][2] += a1 * bq.z; acc[1][3] += a1 * bq.w;
        acc[2][0] += a2 * bq.x; acc[2][1] += a2 * bq.y; acc[2][2] += a2 * bq.z; acc[2][3] += a2 * bq.w;
        acc[3][0] += a3 * bq.x; acc[3][1] += a3 * bq.y; acc[3][2] += a3 * bq.z; acc[3][3] += a3 * bq.w;
    }
#pragma unroll
    for (int i = 0; i < 4; i++)
#pragma unroll
        for (int j = 0; j < 4; j++)
            g_Xin[(size_t)(rb + ty * 4 + i) * NN + cb + tx * 4 + j] = acc[i][j];
}

// ---------------- persistent fused RNN kernel ----------------
// grid = 96: region (3) x coltile (16) x rowtile (2). CTA tile = [64 rows x 32 cols].
// 128 threads = 4 warps, FULLY warp-autonomous: no __syncthreads, no
// __threadfence in the step loop. Flags count warp arrivals (128/region/step);
// each warp gates itself with ld.acquire polls and publishes with red.release
// (counting-semaphore release-sequence => prior stores visible to acquirers).
// Gate placement overlaps latency: rec gate before prologue; cross gate just
// before the first cross-chunk load issue (c==1); WAR gate before epilogue.
// 3-deep cp.async ring; prefetch c+3 AFTER chunk c's mma (ordering load-bearing).
// smem (bf16 elems):
//   W slots: 32 x 2048 at 0      (slot = (mat*8+kc64)*2+part), 32 rows x 64 K
//   A bufs : 3 x 4 x 4096 at 65536  (buf, part*2+sub), 64 rows x 64 K
#define W_SLOT(mat, kc, part) ((((mat) * 8 + (kc)) * 2 + (part)) * 2048)
#define A_OFF 65536
#define A_SLOT(buf, part, sub) (A_OFF + ((buf) * 4 + (part) * 2 + (sub)) * 4096)
#define SMEM_TOTAL ((A_OFF + 12 * 4096) * 2)   // bytes = 229376

// warp loads its own 16 rows of one 128-K chunk (hi+lo): 512 16B units / 32 lanes
__device__ __forceinline__ void load_A_warp(const bf16* hi, const bf16* lo,
                                            int rb, int wr, int kb, bf16* sm,
                                            int buf, int lane) {
#pragma unroll
    for (int u = lane; u < 512; u += 32) {
        int part = u >> 8;                  // 0:hi 1:lo
        int rest = u & 255;
        int sub  = rest >> 7;               // 0/1 : 64-K subtile
        int w    = rest & 127;
        int row  = w >> 3, kk = (w & 7) << 3;
        const bf16* src = (part ? lo : hi) +
            (size_t)(rb + wr * 16 + row) * NN + kb + sub * 64 + kk;
        cp_async16(sm + A_SLOT(buf, part, sub) + swz(wr * 16 + row, kk), src);
    }
}

// load all 6 fragments (24 regs) for k16 index kk of chunk c in buffer buf
__device__ __forceinline__ void ld6(uint32_t* F, const bf16* sm, int buf, int c, int kk,
                                    int ar, int ak_off, int brow0, int bk_off) {
    int sub = kk >> 2;
    int ko  = (kk & 3) << 4;
    int mat = c >> 2;
    int kc  = (c & 3) * 2 + sub;
    const bf16* Ah = sm + A_SLOT(buf, 0, sub);
    const bf16* Al = sm + A_SLOT(buf, 1, sub);
    const bf16* wh = sm + W_SLOT(mat, kc, 0);
    const bf16* wl = sm + W_SLOT(mat, kc, 1);
    ldsm_x4(F + 0,  smaddr(Ah + swz(ar, ko + ak_off)));
    ldsm_x4(F + 4,  smaddr(Al + swz(ar, ko + ak_off)));
    ldsm_x4(F + 8,  smaddr(wh + swz(brow0,      ko + bk_off)));
    ldsm_x4(F + 12, smaddr(wh + swz(brow0 + 16, ko + bk_off)));
    ldsm_x4(F + 16, smaddr(wl + swz(brow0,      ko + bk_off)));
    ldsm_x4(F + 20, smaddr(wl + swz(brow0 + 16, ko + bk_off)));
}

// the 12 mma for one k16 (3-term split: hh, hl, lh)
__device__ __forceinline__ void mma12(float acc[4][4], const uint32_t* F) {
    mma_bf16(acc[0], F + 0, F + 8);
    mma_bf16(acc[1], F + 0, F + 10);
    mma_bf16(acc[2], F + 0, F + 12);
    mma_bf16(acc[3], F + 0, F + 14);
    mma_bf16(acc[0], F + 0, F + 16);
    mma_bf16(acc[1], F + 0, F + 18);
    mma_bf16(acc[2], F + 0, F + 20);
    mma_bf16(acc[3], F + 0, F + 22);
    mma_bf16(acc[0], F + 4, F + 8);
    mma_bf16(acc[1], F + 4, F + 10);
    mma_bf16(acc[2], F + 4, F + 12);
    mma_bf16(acc[3], F + 4, F + 14);
}

__global__ __launch_bounds__(NTHR, 1) void persist_kernel() {
    extern __shared__ bf16 sm[];
    int tid  = threadIdx.x;
    int lane = tid & 31, warp = tid >> 5;   // 4 warps
    int region = blockIdx.x >> 5;
    int rem    = blockIdx.x & 31;
    int ct = rem >> 1, rt = rem & 1;
    int rb = rt * 64, cb = ct * 32;
    int cross = (region + 2) % 3;          // A<-C, B<-A, C<-B
    int nxt   = (region + 1) % 3;          // region that READS our rates
    int wr = warp;                          // warp owns rows wr*16..+16, all 32 cols

    // ---- load resident weights into smem (once) ----
    for (int l = tid; l < 8192; l += NTHR) {
        int slot   = l >> 8;               // 0..31
        int within = l & 255;
        int row = within >> 3, kk = (within & 7) << 3;
        int part   = slot & 1;
        int kc     = (slot >> 1) & 7;
        int mat    = slot >> 4;
        const bf16* src =
            (mat == 0) ? (part ? g_Wrec_lo[region]   : g_Wrec_hi[region])
                       : (part ? g_Wcross_lo[region] : g_Wcross_hi[region]);
        cp_async16(sm + W_SLOT(mat, kc, part) + swz(row, kk),
                   src + (size_t)(cb + row) * NN + kc * 64 + kk);
    }
    cp_commit();
    cp_wait<0>();
    __syncthreads();   // once, outside the step loop

    // ---- persistent leaky state in registers (16 outputs per thread) ----
    float xreg[16];
#pragma unroll
    for (int i = 0; i < 16; i++) xreg[i] = 0.f;

    // fragment addressing (constant across steps)
    int ar = wr * 16 + (lane & 15);
    int ak_off = (lane >> 4) << 3;
    int brow0 = ((lane >> 4) << 3) + (lane & 7);   // n 0-15 block
    int bk_off = ((lane >> 3) & 1) << 3;

    int g = lane >> 2, q = lane & 3;
    int row0 = rb + wr * 16 + g;                   // batch row (and +8)

    for (int t = 1; t < TT; t++) {
        unsigned tgt1 = (unsigned)(ARRV * (t - 1));

        int p_in = (t - 1) % 3, p_out = t % 3;
        const bf16* rhi[2] = { &g_r_hi[p_in][region * BB * NN], &g_r_hi[p_in][cross * BB * NN] };
        const bf16* rlo[2] = { &g_r_lo[p_in][region * BB * NN], &g_r_lo[p_in][cross * BB * NN] };

        // Xin prefetch (region 0) BEFORE any gate — fully independent data
        float xin[16];
        if (region == 0) {
            const float* xp = g_Xin + (size_t)t * BB * NN;
#pragma unroll
            for (int nh = 0; nh < 4; nh++)
#pragma unroll
                for (int i2 = 0; i2 < 2; i2++) {
                    float2 v = *(const float2*)(xp + (size_t)(row0 + i2 * 8) * NN
                                                + cb + nh * 8 + q * 2);
                    xin[nh * 4 + i2 * 2 + 0] = v.x;
                    xin[nh * 4 + i2 * 2 + 1] = v.y;
                }
        }

        float acc[4][4];
#pragma unroll
        for (int nh = 0; nh < 4; nh++)
#pragma unroll
            for (int i = 0; i < 4; i++) acc[nh][i] = 0.f;

        // ---- gate 1: own-region producers (rec chunks 0-3) ----
        wait_flag(&g_flag[region], tgt1);

        // prologue: 3-deep per-warp pipeline (chunks 0,1,2 — all rec)
        load_A_warp(rhi[0], rlo[0], rb, wr, 0, sm, 0, lane);   cp_commit();
        load_A_warp(rhi[0], rlo[0], rb, wr, 128, sm, 1, lane); cp_commit();
        load_A_warp(rhi[0], rlo[0], rb, wr, 256, sm, 2, lane); cp_commit();

        uint32_t F0[24], F1[24];
        int buf = 0;
#pragma unroll 1
        for (int c = 0; c < 8; c++) {           // 8 chunks x 128 K
            cp_wait<2>();                        // chunk c landed (own warp's groups)
            __syncwarp();

            // ---- gate 2: cross producers, just before first cross load issue
            if (c == 1) wait_flag(&g_flag[cross], tgt1);

            // software-pipelined 8 x k16: ldsm(kk+1) issued before mma(kk)
            ld6(F0, sm, buf, c, 0, ar, ak_off, brow0, bk_off);
#pragma unroll
            for (int kk = 0; kk < 8; kk++) {
                uint32_t* cur = (kk & 1) ? F1 : F0;
                uint32_t* nxtF = (kk & 1) ? F0 : F1;
                if (kk < 7)
                    ld6(nxtF, sm, buf, c, kk + 1, ar, ak_off, brow0, bk_off);
                mma12(acc, cur);
            }

            // prefetch into the just-freed buffer (AFTER the reads — ordering
            // is load-bearing; issuing before the mma loop is a race)
            if (c < 5) {
                int c3 = c + 3;
                int m2 = c3 >> 2;
                int kb = (c3 & 3) * 128;
                load_A_warp(rhi[m2], rlo[m2], rb, wr, kb, sm, buf, lane);
                cp_commit();
            }
            if (++buf == 3) buf = 0;
        }

        // ---- gate 3 (WAR): readers of buffer t%3 must be done with step t-2
        if (t >= 2) wait_flag(&g_flag[nxt], (unsigned)(ARRV * (t - 2)));

        // ---- epilogue: leaky update + fast tanh + split-store rates ----
#pragma unroll
        for (int nh = 0; nh < 4; nh++) {
#pragma unroll
            for (int i2 = 0; i2 < 2; i2++) {
                int row = row0 + i2 * 8;
                int col = cb + nh * 8 + q * 2;
                float s0 = acc[nh][i2 * 2 + 0];
                float s1 = acc[nh][i2 * 2 + 1];
                if (region == 0) {
                    s0 += xin[nh * 4 + i2 * 2 + 0];
                    s1 += xin[nh * 4 + i2 * 2 + 1];
                }
                int xi = nh * 4 + i2 * 2;
                float x0 = 0.9f * xreg[xi + 0] + 0.1f * s0;
                float x1 = 0.9f * xreg[xi + 1] + 0.1f * s1;
                xreg[xi + 0] = x0;
                xreg[xi + 1] = x1;
                float r0 = ftanh(x0), r1 = ftanh(x1);
                bf16 h0 = __float2bfloat16(r0);
                bf16 h1 = __float2bfloat16(r1);
                bf16 l0 = __float2bfloat16(r0 - __bfloat162float(h0));
                bf16 l1 = __float2bfloat16(r1 - __bfloat162float(h1));
                int idx = region * BB * NN + row * NN + col;
                *(__nv_bfloat162*)&g_r_hi[p_out][idx] = __nv_bfloat162(h0, h1);
                *(__nv_bfloat162*)&g_r_lo[p_out][idx] = __nv_bfloat162(l0, l1);
                if (region == 2)
                    *(float2*)&g_hist[(size_t)(t - 1) * BB * NN + (size_t)row * NN + col] =
                        make_float2(r0, r1);
            }
        }

        // publish: release-add orders this warp's prior stores for acquirers
        __syncwarp();
        if (lane == 0) red_rel_add(&g_flag[region]);
    }
}

// ---------------- final readout: out = rC_hist @ W_out.T ----------------
__global__ void out_kernel(const float* Wout, float* out) {
    __shared__ float sw0[512], sw1[512];
    int bt = blockIdx.x;
    int tid = threadIdx.x; // 128 threads, one batch row each
    for (int j = tid; j < 512; j += 128) { sw0[j] = Wout[j]; sw1[j] = Wout[512 + j]; }
    __syncthreads();
    const float* row = g_hist + (size_t)bt * BB * NN + (size_t)tid * NN;
    float s0 = 0.f, s1 = 0.f;
    for (int j = 0; j < 512; j += 4) {
        float4 v = *(const float4*)(row + j);
        s0 += v.x * sw0[j] + v.y * sw0[j + 1] + v.z * sw0[j + 2] + v.w * sw0[j + 3];
        s1 += v.x * sw1[j] + v.y * sw1[j + 1] + v.z * sw1[j + 2] + v.w * sw1[j + 3];
    }
    out[((size_t)bt * BB + tid) * 2 + 0] = s0;
    out[((size_t)bt * BB + tid) * 2 + 1] = s1;
}

// ---------------- launch ----------------
extern "C" void kernel_launch(void* const* d_in, const int* in_sizes, int n_in,
                              void* d_out, int out_size) {
    const float* X     = (const float*)d_in[0];
    const float* WrecA = (const float*)d_in[1];
    const float* WrecB = (const float*)d_in[2];
    const float* WrecC = (const float*)d_in[3];
    const float* W_AB  = (const float*)d_in[4];
    const float* W_BC  = (const float*)d_in[5];
    const float* W_CA  = (const float*)d_in[6];
    const float* W_in  = (const float*)d_in[7];
    const float* W_out = (const float*)d_in[8];

    cudaFuncSetAttribute(persist_kernel, cudaFuncAttributeMaxDynamicSharedMemorySize, SMEM_TOTAL);

    init_zero<<<768, 256>>>();
    split_w<<<6144, 256>>>(WrecA, WrecB, WrecC, W_CA, W_AB, W_BC);
    dim3 pg(TT * BB / 64, NN / 64);
    precompute_in<<<pg, 256>>>(X, W_in);
    persist_kernel<<<GRID, NTHR, SMEM_TOTAL>>>();
    out_kernel<<<TT - 1, 128>>>(W_out, (float*)d_out);
}